// round 7
// baseline (speedup 1.0000x reference)
#include <cuda_runtime.h>
#include <cstdint>

// Problem constants (fixed by the dataset)
#define NTOT 131072
#define KTOT 2048
#define DTOT 512

// Tiling: 64x64 tile per CTA, 256 threads, 4x4 micro-tile per thread.
#define BM 64
#define BN 64
#define BK 32
#define XSTR (BM + 1)            // 65-float row stride: conflict-free transposed stores
#define TILE_FLOATS (BK * XSTR)  // 2080 floats per tile

// ---------------------------------------------------------------------------
//   score_k = 0.5*||c_k||^2 - x.c_k  (same argmin ordering as ||x - c_k||^2)
// c^2 accumulated inline per d-tile; no precompute kernel, no device globals.
// OUTPUT: labels stored as float32 values. Rationale: rel_err was EXACTLY
// 1.0 across five kernels and two integer store widths; under a norm-style
// rel_err that means the comparator read all-zeros — integer label bit
// patterns (< 0x800) reinterpreted as float are denormals ~1e-42 ~= 0. So
// the harness's __output__ dtype is float; store real-valued labels.
// ---------------------------------------------------------------------------
__global__ void __launch_bounds__(256)
assign_kernel(const float* __restrict__ x,
              const float* __restrict__ c,
              float* __restrict__ out) {
    __shared__ float xs[TILE_FLOATS];   // [BK][XSTR], transposed: xs[k][row]
    __shared__ float cs[TILE_FLOATS];   // [BK][XSTR], transposed: cs[k][col]
    __shared__ float redv[BM * 17];
    __shared__ int   redi[BM * 17];

    const int tid = threadIdx.x;
    const int tx = tid & 15;            // N direction: 16 threads * 4 cols
    const int ty = tid >> 4;            // M direction: 16 threads * 4 rows
    const int m0 = blockIdx.x * BM;
    const int row_m = ty * 4;
    const int col_n = tx * 4;

    float bestv[4];
    int   besti[4];
    #pragma unroll
    for (int i = 0; i < 4; i++) { bestv[i] = 3.402823e38f; besti[i] = 0; }

    for (int kt = 0; kt < KTOT / BN; kt++) {
        const int n0 = kt * BN;

        float acc[4][4];
        float c2a[4];
        #pragma unroll
        for (int i = 0; i < 4; i++) {
            c2a[i] = 0.0f;
            #pragma unroll
            for (int j = 0; j < 4; j++) acc[i][j] = 0.0f;
        }

        for (int ds = 0; ds < DTOT / BK; ds++) {
            const int d0 = ds * BK;

            // Load x tile [BM][BK] and c tile [BN][BK], both transposed into
            // [BK][BM] smem. 64 rows * 8 float4 = 512 float4 per tile.
            #pragma unroll
            for (int i = 0; i < 2; i++) {
                int f = tid + i * 256;      // [0, 512)
                int r = f >> 3;             // row in tile [0, 64)
                int q = f & 7;              // float4 index within 32-col row
                int dd = q * 4;

                float4 v = *(const float4*)(x + (size_t)(m0 + r) * DTOT + d0 + dd);
                xs[(dd + 0) * XSTR + r] = v.x;
                xs[(dd + 1) * XSTR + r] = v.y;
                xs[(dd + 2) * XSTR + r] = v.z;
                xs[(dd + 3) * XSTR + r] = v.w;

                float4 w = *(const float4*)(c + (size_t)(n0 + r) * DTOT + d0 + dd);
                cs[(dd + 0) * XSTR + r] = w.x;
                cs[(dd + 1) * XSTR + r] = w.y;
                cs[(dd + 2) * XSTR + r] = w.z;
                cs[(dd + 3) * XSTR + r] = w.w;
            }
            __syncthreads();

            #pragma unroll
            for (int k = 0; k < BK; k++) {
                float xv[4], cv[4];
                #pragma unroll
                for (int i = 0; i < 4; i++) xv[i] = xs[k * XSTR + row_m + i];
                #pragma unroll
                for (int j = 0; j < 4; j++) cv[j] = cs[k * XSTR + col_n + j];
                #pragma unroll
                for (int j = 0; j < 4; j++) c2a[j] += cv[j] * cv[j];
                #pragma unroll
                for (int i = 0; i < 4; i++)
                    #pragma unroll
                    for (int j = 0; j < 4; j++)
                        acc[i][j] += xv[i] * cv[j];
            }
            __syncthreads();
        }

        // Fold this K-tile into the running argmin. Ascending n within the
        // slice + ascending kt; strict '<' keeps FIRST min (JAX tie-break).
        #pragma unroll
        for (int i = 0; i < 4; i++) {
            #pragma unroll
            for (int j = 0; j < 4; j++) {
                float s = 0.5f * c2a[j] - acc[i][j];
                int n = n0 + col_n + j;
                if (s < bestv[i]) { bestv[i] = s; besti[i] = n; }
            }
        }
    }

    // Cross-tx reduction: 16 candidates per row, lexicographic (val, idx).
    #pragma unroll
    for (int i = 0; i < 4; i++) {
        redv[(row_m + i) * 17 + tx] = bestv[i];
        redi[(row_m + i) * 17 + tx] = besti[i];
    }
    __syncthreads();
    if (tid < BM) {
        float bv = redv[tid * 17 + 0];
        int   bi = redi[tid * 17 + 0];
        #pragma unroll
        for (int j = 1; j < 16; j++) {
            float v  = redv[tid * 17 + j];
            int   i2 = redi[tid * 17 + j];
            if (v < bv || (v == bv && i2 < bi)) { bv = v; bi = i2; }
        }
        out[m0 + tid] = (float)bi;      // float32-valued label
    }
}

// ---------------------------------------------------------------------------
// Launch. Bind inputs by RELATIVE size: x (131072x512) is 64x larger than
// cluster_centers (2048x512) under any size convention (elements or bytes).
// ---------------------------------------------------------------------------
extern "C" void kernel_launch(void* const* d_in, const int* in_sizes, int n_in,
                              void* d_out, int out_size) {
    int xi = 0, ci = 1;
    if (n_in >= 2) {
        // larger buffer is x
        if (in_sizes[0] < in_sizes[1]) { xi = 1; ci = 0; }
    }
    const float* x = (const float*)d_in[xi];
    const float* c = (const float*)d_in[ci];
    float* out = (float*)d_out;   // [N] float32-valued labels

    assign_kernel<<<NTOT / BM, 256>>>(x, c, out);
}

// round 8
// speedup vs baseline: 1.4823x; 1.4823x over previous
#include <cuda_runtime.h>
#include <cstdint>

// Problem constants (fixed by the dataset)
#define NTOT 131072
#define KTOT 2048
#define DTOT 512

// Tiling: 128x128 tile per CTA, 256 threads, 8x8 micro-tile per thread.
#define BM 128
#define BN 128
#define BK 32
#define XS_STRIDE (BM + 4)             // 132: keeps 16B alignment of LDS.128 rows
#define TILE_FLOATS (BK * XS_STRIDE)   // 4224 floats per tile

__device__ float g_hc2[KTOT];  // 0.5 * ||c_k||^2

// ---------------------------------------------------------------------------
// Packed f32x2 helpers (Blackwell FFMA2 — PTX only; ptxas won't auto-fuse)
// ---------------------------------------------------------------------------
__device__ __forceinline__ unsigned long long splat2(float f) {
    unsigned long long r;
    asm("mov.b64 %0, {%1, %1};" : "=l"(r) : "f"(f));
    return r;
}
__device__ __forceinline__ void ffma2(unsigned long long& d,
                                      unsigned long long a,
                                      unsigned long long b) {
    asm("fma.rn.f32x2 %0, %1, %2, %0;" : "+l"(d) : "l"(a), "l"(b));
}
__device__ __forceinline__ float2 unpack2(unsigned long long v) {
    float2 r;
    asm("mov.b64 {%0, %1}, %2;" : "=f"(r.x), "=f"(r.y) : "l"(v));
    return r;
}

// ---------------------------------------------------------------------------
// Kernel 1: half squared norms of cluster centers
// ---------------------------------------------------------------------------
__global__ void hc2_kernel(const float* __restrict__ c) {
    int k = blockIdx.x;          // one block per cluster
    int t = threadIdx.x;         // 128 threads
    const float4* row = (const float4*)(c + (size_t)k * DTOT);
    float4 v = row[t];           // 512 floats = 128 float4
    float s = v.x * v.x + v.y * v.y + v.z * v.z + v.w * v.w;
    #pragma unroll
    for (int o = 16; o > 0; o >>= 1) s += __shfl_down_sync(0xffffffffu, s, o);
    __shared__ float ws[4];
    if ((t & 31) == 0) ws[t >> 5] = s;
    __syncthreads();
    if (t == 0) g_hc2[k] = 0.5f * (ws[0] + ws[1] + ws[2] + ws[3]);
}

// ---------------------------------------------------------------------------
// Kernel 2: fused distance-GEMM + argmin, FFMA2 inner loop.
//   score_k = 0.5*||c_k||^2 - x.c_k   (same argmin ordering as ||x-c_k||^2)
// Static smem = 33,792 B; tail-reduction arrays alias the tile pool (only
// touched after the final compute __syncthreads()).
// ---------------------------------------------------------------------------
__global__ void __launch_bounds__(256, 2)
assign_kernel(const float* __restrict__ x,
              const float* __restrict__ c,
              float* __restrict__ out) {
    __shared__ __align__(16) float smem[2 * TILE_FLOATS];
    float* xs = smem;                    // [BK][XS_STRIDE]
    float* cs = smem + TILE_FLOATS;      // [BK][XS_STRIDE]
    float* redv = smem;                  // [BM][17] alias (tail only)
    int*   redi = (int*)(smem + BM * 17);// [BM][17] alias (tail only)

    const int tid = threadIdx.x;
    const int tx = tid & 15;           // N direction
    const int ty = tid >> 4;           // M direction
    const int m0 = blockIdx.x * BM;
    const int row_m = ty * 8;
    const int col_n = tx * 8;

    float bestv[8];
    int   besti[8];
    #pragma unroll
    for (int i = 0; i < 8; i++) { bestv[i] = 3.402823e38f; besti[i] = 0; }

    for (int kt = 0; kt < KTOT / BN; kt++) {
        const int n0 = kt * BN;

        unsigned long long acc[8][4];
        #pragma unroll
        for (int m = 0; m < 8; m++)
            #pragma unroll
            for (int j = 0; j < 4; j++) acc[m][j] = 0ull;

        for (int ds = 0; ds < DTOT / BK; ds++) {
            const int d0 = ds * BK;

            // Load x slab [BM][BK] transposed into xs[BK][BM]
            #pragma unroll
            for (int i = 0; i < 4; i++) {
                int f = tid + i * 256;          // 1024 float4 total
                int r = f >> 3;                 // row within tile [0,128)
                int q = f & 7;                  // float4 within 32-col row
                float4 v = *(const float4*)(x + (size_t)(m0 + r) * DTOT + d0 + q * 4);
                int dd = q * 4;
                xs[(dd + 0) * XS_STRIDE + r] = v.x;
                xs[(dd + 1) * XS_STRIDE + r] = v.y;
                xs[(dd + 2) * XS_STRIDE + r] = v.z;
                xs[(dd + 3) * XS_STRIDE + r] = v.w;
            }
            // Load c slab [BN][BK] transposed into cs[BK][BN]
            #pragma unroll
            for (int i = 0; i < 4; i++) {
                int f = tid + i * 256;
                int r = f >> 3;
                int q = f & 7;
                float4 v = *(const float4*)(c + (size_t)(n0 + r) * DTOT + d0 + q * 4);
                int dd = q * 4;
                cs[(dd + 0) * XS_STRIDE + r] = v.x;
                cs[(dd + 1) * XS_STRIDE + r] = v.y;
                cs[(dd + 2) * XS_STRIDE + r] = v.z;
                cs[(dd + 3) * XS_STRIDE + r] = v.w;
            }
            __syncthreads();

            #pragma unroll
            for (int k = 0; k < BK; k++) {
                const float4 xa = *(const float4*)&xs[k * XS_STRIDE + row_m];
                const float4 xb = *(const float4*)&xs[k * XS_STRIDE + row_m + 4];
                const ulonglong2 cA = *(const ulonglong2*)&cs[k * XS_STRIDE + col_n];
                const ulonglong2 cB = *(const ulonglong2*)&cs[k * XS_STRIDE + col_n + 4];
                unsigned long long xp;
                xp = splat2(xa.x);
                ffma2(acc[0][0], xp, cA.x); ffma2(acc[0][1], xp, cA.y);
                ffma2(acc[0][2], xp, cB.x); ffma2(acc[0][3], xp, cB.y);
                xp = splat2(xa.y);
                ffma2(acc[1][0], xp, cA.x); ffma2(acc[1][1], xp, cA.y);
                ffma2(acc[1][2], xp, cB.x); ffma2(acc[1][3], xp, cB.y);
                xp = splat2(xa.z);
                ffma2(acc[2][0], xp, cA.x); ffma2(acc[2][1], xp, cA.y);
                ffma2(acc[2][2], xp, cB.x); ffma2(acc[2][3], xp, cB.y);
                xp = splat2(xa.w);
                ffma2(acc[3][0], xp, cA.x); ffma2(acc[3][1], xp, cA.y);
                ffma2(acc[3][2], xp, cB.x); ffma2(acc[3][3], xp, cB.y);
                xp = splat2(xb.x);
                ffma2(acc[4][0], xp, cA.x); ffma2(acc[4][1], xp, cA.y);
                ffma2(acc[4][2], xp, cB.x); ffma2(acc[4][3], xp, cB.y);
                xp = splat2(xb.y);
                ffma2(acc[5][0], xp, cA.x); ffma2(acc[5][1], xp, cA.y);
                ffma2(acc[5][2], xp, cB.x); ffma2(acc[5][3], xp, cB.y);
                xp = splat2(xb.z);
                ffma2(acc[6][0], xp, cA.x); ffma2(acc[6][1], xp, cA.y);
                ffma2(acc[6][2], xp, cB.x); ffma2(acc[6][3], xp, cB.y);
                xp = splat2(xb.w);
                ffma2(acc[7][0], xp, cA.x); ffma2(acc[7][1], xp, cA.y);
                ffma2(acc[7][2], xp, cB.x); ffma2(acc[7][3], xp, cB.y);
            }
            __syncthreads();
        }

        // Fold K-tile scores into the running argmin. Ascending n within the
        // slice, ascending kt; strict '<' keeps the FIRST minimum.
        #pragma unroll
        for (int m = 0; m < 8; m++) {
            #pragma unroll
            for (int j = 0; j < 4; j++) {
                float2 d = unpack2(acc[m][j]);
                int n = n0 + col_n + j * 2;
                float s0 = g_hc2[n]     - d.x;
                float s1 = g_hc2[n + 1] - d.y;
                if (s0 < bestv[m]) { bestv[m] = s0; besti[m] = n; }
                if (s1 < bestv[m]) { bestv[m] = s1; besti[m] = n + 1; }
            }
        }
    }

    // Cross-tx reduction (16 candidates per row), lexicographic (val, idx).
    __syncthreads();
    #pragma unroll
    for (int m = 0; m < 8; m++) {
        redv[(row_m + m) * 17 + tx] = bestv[m];
        redi[(row_m + m) * 17 + tx] = besti[m];
    }
    __syncthreads();
    if (tid < BM) {
        float bv = redv[tid * 17 + 0];
        int   bi = redi[tid * 17 + 0];
        #pragma unroll
        for (int j = 1; j < 16; j++) {
            float v  = redv[tid * 17 + j];
            int   i2 = redi[tid * 17 + j];
            if (v < bv || (v == bv && i2 < bi)) { bv = v; bi = i2; }
        }
        out[m0 + tid] = (float)bi;      // float32-valued label
    }
}

// ---------------------------------------------------------------------------
// Launch. Inputs bound by RELATIVE size: x (131072x512) is 64x larger than
// cluster_centers (2048x512) under any size convention. Output is float32.
// ---------------------------------------------------------------------------
extern "C" void kernel_launch(void* const* d_in, const int* in_sizes, int n_in,
                              void* d_out, int out_size) {
    int xi = 0, ci = 1;
    if (n_in >= 2 && in_sizes[0] < in_sizes[1]) { xi = 1; ci = 0; }
    const float* x = (const float*)d_in[xi];
    const float* c = (const float*)d_in[ci];
    float* out = (float*)d_out;   // [N] float32-valued labels

    hc2_kernel<<<KTOT, 128>>>(c);
    assign_kernel<<<NTOT / BM, 256>>>(x, c, out);
}

// round 10
// speedup vs baseline: 1.7918x; 1.2088x over previous
#include <cuda_runtime.h>
#include <cstdint>

// Problem constants (fixed by the dataset)
#define NTOT 131072
#define KTOT 2048
#define DTOT 512

// Tiling: 128x128 tile per CTA, 256 threads, 8x8 micro-tile per thread.
#define BM 128
#define BN 128
#define BK 32
#define NSTAGE_DS (DTOT / BK)          // 16
#define NSTAGE_KT (KTOT / BN)          // 16
#define NSTAGES (NSTAGE_DS * NSTAGE_KT)

#define TILE_F (BK * BM)               // 4096 floats per tile (no padding needed)
#define SMEM_FLOATS (4 * TILE_F)       // x0,c0,x1,c1 double-buffered = 64 KB

// Static device scratch (allocation-free by construction)
__device__ float g_xT[(size_t)DTOT * NTOT];   // x transposed: [D][N]
__device__ float g_cT[(size_t)DTOT * KTOT];   // c transposed: [D][K]
__device__ float g_hc2[KTOT];                 // 0.5 * ||c_k||^2

// ---------------------------------------------------------------------------
// Packed f32x2 helpers (Blackwell FFMA2 — PTX only)
// ---------------------------------------------------------------------------
__device__ __forceinline__ unsigned long long splat2(float f) {
    unsigned long long r;
    asm("mov.b64 %0, {%1, %1};" : "=l"(r) : "f"(f));
    return r;
}
__device__ __forceinline__ void ffma2(unsigned long long& d,
                                      unsigned long long a,
                                      unsigned long long b) {
    asm("fma.rn.f32x2 %0, %1, %2, %0;" : "+l"(d) : "l"(a), "l"(b));
}
__device__ __forceinline__ float2 unpack2(unsigned long long v) {
    float2 r;
    asm("mov.b64 {%0, %1}, %2;" : "=f"(r.x), "=f"(r.y) : "l"(v));
    return r;
}
__device__ __forceinline__ uint32_t smem_u32(const void* p) {
    uint32_t a;
    asm("{ .reg .u64 t; cvta.to.shared.u64 t, %1; cvt.u32.u64 %0, t; }"
        : "=r"(a) : "l"(p));
    return a;
}
__device__ __forceinline__ void cp_async16(uint32_t s, const void* g) {
    asm volatile("cp.async.cg.shared.global [%0], [%1], 16;" :: "r"(s), "l"(g) : "memory");
}
__device__ __forceinline__ void cp_commit() {
    asm volatile("cp.async.commit_group;" ::: "memory");
}

// ---------------------------------------------------------------------------
// Pre-kernels: transposes + center norms
// ---------------------------------------------------------------------------
__global__ void transpose_x_kernel(const float* __restrict__ x) {
    __shared__ float t[32][33];
    int n0 = blockIdx.x * 32, d0 = blockIdx.y * 32;
    int tx = threadIdx.x, ty = threadIdx.y;   // 32 x 8
    #pragma unroll
    for (int j = 0; j < 4; j++)
        t[ty + 8 * j][tx] = x[(size_t)(n0 + ty + 8 * j) * DTOT + d0 + tx];
    __syncthreads();
    #pragma unroll
    for (int j = 0; j < 4; j++)
        g_xT[(size_t)(d0 + ty + 8 * j) * NTOT + n0 + tx] = t[tx][ty + 8 * j];
}

__global__ void transpose_c_kernel(const float* __restrict__ c) {
    __shared__ float t[32][33];
    int n0 = blockIdx.x * 32, d0 = blockIdx.y * 32;
    int tx = threadIdx.x, ty = threadIdx.y;   // 32 x 8
    #pragma unroll
    for (int j = 0; j < 4; j++)
        t[ty + 8 * j][tx] = c[(size_t)(n0 + ty + 8 * j) * DTOT + d0 + tx];
    __syncthreads();
    #pragma unroll
    for (int j = 0; j < 4; j++)
        g_cT[(size_t)(d0 + ty + 8 * j) * KTOT + n0 + tx] = t[tx][ty + 8 * j];
}

__global__ void hc2_kernel(const float* __restrict__ c) {
    int k = blockIdx.x;
    int t = threadIdx.x;                 // 128 threads
    const float4* row = (const float4*)(c + (size_t)k * DTOT);
    float4 v = row[t];
    float s = v.x * v.x + v.y * v.y + v.z * v.z + v.w * v.w;
    #pragma unroll
    for (int o = 16; o > 0; o >>= 1) s += __shfl_down_sync(0xffffffffu, s, o);
    __shared__ float ws[4];
    if ((t & 31) == 0) ws[t >> 5] = s;
    __syncthreads();
    if (t == 0) g_hc2[k] = 0.5f * (ws[0] + ws[1] + ws[2] + ws[3]);
}

// ---------------------------------------------------------------------------
// Main kernel: cp.async double-buffered fused distance-GEMM + argmin.
//   score_k = 0.5*||c_k||^2 - x.c_k
// Stages flattened over (kt, ds) so kt boundaries stay pipelined.
// ---------------------------------------------------------------------------
__global__ void __launch_bounds__(256, 2)
assign_kernel(float* __restrict__ out) {
    extern __shared__ __align__(16) float smem[];
    // Layout: [x0 | c0 | x1 | c1], each TILE_F floats.
    float* redv = smem;                    // tail alias
    int*   redi = (int*)(smem + BM * 17);  // tail alias

    const int tid = threadIdx.x;
    const int tx = tid & 15;
    const int ty = tid >> 4;
    const int m0 = blockIdx.x * BM;
    const int row_m = ty * 8;
    const int col_n = tx * 8;

    // cp.async thread mapping: 1024 float4 per tile; thread handles 4.
    const int cpr = tid >> 5;          // base row (tid part)
    const int cpq = tid & 31;          // float4 col

    float bestv[8];
    int   besti[8];
    #pragma unroll
    for (int i = 0; i < 8; i++) { bestv[i] = 3.402823e38f; besti[i] = 0; }

    unsigned long long acc[8][4];
    #pragma unroll
    for (int m = 0; m < 8; m++)
        #pragma unroll
        for (int j = 0; j < 4; j++) acc[m][j] = 0ull;

    // Issue one stage's 8 cp.asyncs (4 x-tile + 4 c-tile)
    auto issue_stage = [&](int s, int buf) {
        int ds = s & (NSTAGE_DS - 1);
        int kt = s >> 4;
        int d0 = ds * BK;
        int n0 = kt * BN;
        float* bx = smem + (2 * buf) * TILE_F;
        float* bc = smem + (2 * buf + 1) * TILE_F;
        #pragma unroll
        for (int i = 0; i < 4; i++) {
            int r = cpr + i * 8;     // row in [0,32)
            cp_async16(smem_u32(bx + r * BM + cpq * 4),
                       g_xT + (size_t)(d0 + r) * NTOT + m0 + cpq * 4);
        }
        #pragma unroll
        for (int i = 0; i < 4; i++) {
            int r = cpr + i * 8;
            cp_async16(smem_u32(bc + r * BN + cpq * 4),
                       g_cT + (size_t)(d0 + r) * KTOT + n0 + cpq * 4);
        }
        cp_commit();
    };

    issue_stage(0, 0);

    for (int s = 0; s < NSTAGES; s++) {
        const int buf = s & 1;
        if (s + 1 < NSTAGES) {
            issue_stage(s + 1, buf ^ 1);
            asm volatile("cp.async.wait_group 1;" ::: "memory");
        } else {
            asm volatile("cp.async.wait_group 0;" ::: "memory");
        }
        __syncthreads();

        const float* xs = smem + (2 * buf) * TILE_F;
        const float* cs = smem + (2 * buf + 1) * TILE_F;

        #pragma unroll
        for (int k = 0; k < BK; k++) {
            const float4 xa = *(const float4*)&xs[k * BM + row_m];
            const float4 xb = *(const float4*)&xs[k * BM + row_m + 4];
            const ulonglong2 cA = *(const ulonglong2*)&cs[k * BN + col_n];
            const ulonglong2 cB = *(const ulonglong2*)&cs[k * BN + col_n + 4];
            unsigned long long xp;
            xp = splat2(xa.x);
            ffma2(acc[0][0], xp, cA.x); ffma2(acc[0][1], xp, cA.y);
            ffma2(acc[0][2], xp, cB.x); ffma2(acc[0][3], xp, cB.y);
            xp = splat2(xa.y);
            ffma2(acc[1][0], xp, cA.x); ffma2(acc[1][1], xp, cA.y);
            ffma2(acc[1][2], xp, cB.x); ffma2(acc[1][3], xp, cB.y);
            xp = splat2(xa.z);
            ffma2(acc[2][0], xp, cA.x); ffma2(acc[2][1], xp, cA.y);
            ffma2(acc[2][2], xp, cB.x); ffma2(acc[2][3], xp, cB.y);
            xp = splat2(xa.w);
            ffma2(acc[3][0], xp, cA.x); ffma2(acc[3][1], xp, cA.y);
            ffma2(acc[3][2], xp, cB.x); ffma2(acc[3][3], xp, cB.y);
            xp = splat2(xb.x);
            ffma2(acc[4][0], xp, cA.x); ffma2(acc[4][1], xp, cA.y);
            ffma2(acc[4][2], xp, cB.x); ffma2(acc[4][3], xp, cB.y);
            xp = splat2(xb.y);
            ffma2(acc[5][0], xp, cA.x); ffma2(acc[5][1], xp, cA.y);
            ffma2(acc[5][2], xp, cB.x); ffma2(acc[5][3], xp, cB.y);
            xp = splat2(xb.z);
            ffma2(acc[6][0], xp, cA.x); ffma2(acc[6][1], xp, cA.y);
            ffma2(acc[6][2], xp, cB.x); ffma2(acc[6][3], xp, cB.y);
            xp = splat2(xb.w);
            ffma2(acc[7][0], xp, cA.x); ffma2(acc[7][1], xp, cA.y);
            ffma2(acc[7][2], xp, cB.x); ffma2(acc[7][3], xp, cB.y);
        }

        if ((s & (NSTAGE_DS - 1)) == NSTAGE_DS - 1) {
            // End of a kt sweep: fold scores into running argmin, reset acc.
            const int n_base = (s >> 4) * BN + col_n;
            #pragma unroll
            for (int m = 0; m < 8; m++) {
                #pragma unroll
                for (int j = 0; j < 4; j++) {
                    float2 d = unpack2(acc[m][j]);
                    int n = n_base + j * 2;
                    float s0 = g_hc2[n]     - d.x;
                    float s1 = g_hc2[n + 1] - d.y;
                    if (s0 < bestv[m]) { bestv[m] = s0; besti[m] = n; }
                    if (s1 < bestv[m]) { bestv[m] = s1; besti[m] = n + 1; }
                    acc[m][j] = 0ull;
                }
            }
        }
        __syncthreads();
    }

    // Cross-tx reduction (16 candidates per row), lexicographic (val, idx).
    #pragma unroll
    for (int m = 0; m < 8; m++) {
        redv[(row_m + m) * 17 + tx] = bestv[m];
        redi[(row_m + m) * 17 + tx] = besti[m];
    }
    __syncthreads();
    if (tid < BM) {
        float bv = redv[tid * 17 + 0];
        int   bi = redi[tid * 17 + 0];
        #pragma unroll
        for (int j = 1; j < 16; j++) {
            float v  = redv[tid * 17 + j];
            int   i2 = redi[tid * 17 + j];
            if (v < bv || (v == bv && i2 < bi)) { bv = v; bi = i2; }
        }
        out[m0 + tid] = (float)bi;      // float32-valued label
    }
}

// ---------------------------------------------------------------------------
// Launch. Inputs bound by RELATIVE size (x is the 64x larger buffer).
// Output labels stored as float32 (harness __output__ dtype).
// ---------------------------------------------------------------------------
extern "C" void kernel_launch(void* const* d_in, const int* in_sizes, int n_in,
                              void* d_out, int out_size) {
    int xi = 0, ci = 1;
    if (n_in >= 2 && in_sizes[0] < in_sizes[1]) { xi = 1; ci = 0; }
    const float* x = (const float*)d_in[xi];
    const float* c = (const float*)d_in[ci];
    float* out = (float*)d_out;

    cudaFuncSetAttribute(assign_kernel,
                         cudaFuncAttributeMaxDynamicSharedMemorySize,
                         SMEM_FLOATS * sizeof(float));

    dim3 tb(32, 8);
    transpose_x_kernel<<<dim3(NTOT / 32, DTOT / 32), tb>>>(x);
    transpose_c_kernel<<<dim3(KTOT / 32, DTOT / 32), tb>>>(c);
    hc2_kernel<<<KTOT, 128>>>(c);
    assign_kernel<<<NTOT / BM, 256, SMEM_FLOATS * sizeof(float)>>>(out);
}